// round 9
// baseline (speedup 1.0000x reference)
#include <cuda_runtime.h>
#include <stdint.h>
#include <math.h>

#define NTOK 65536
#define DIM  512
#define KCB  512
#define NDsz ((size_t)NTOK * (size_t)DIM)
typedef unsigned long long ull;

// ---- scratch (R1-proven fp32 flow) ----
__device__ float  g_X[NDsz];
__device__ float  g_Z[NDsz];
__device__ float  g_xnorm[NTOK];
__device__ float  g_enorm[KCB];
__device__ float  g_colsum[KCB];
__device__ double g_sse;

// ---- packed fp32x2 helpers ----
__device__ __forceinline__ void fma2(ull& c, ull a, ull b) {
    asm("fma.rn.f32x2 %0, %1, %2, %0;" : "+l"(c) : "l"(a), "l"(b));
}
__device__ __forceinline__ ull dup2(float v) {
    union { ull u; float2 f; } x; x.f = make_float2(v, v); return x.u;
}
__device__ __forceinline__ float2 up2(ull v) {
    union { ull u; float2 f; } x; x.u = v; return x.f;
}
union U4 { float4 f; ull u[2]; };

// ---------------- init (R1 verbatim) ----------------
__global__ void init_kernel() {
    int t = threadIdx.x;
    if (t < KCB) g_colsum[t] = 0.f;
    if (t == 0)  g_sse = 0.0;
}

// ---- row norms (R1 verbatim) ----
__global__ void rownorm2_kernel(const float* __restrict__ Aext, int mode, int rows) {
    int lane = threadIdx.x & 31;
    int warp = threadIdx.x >> 5;
    int row  = blockIdx.x * 8 + warp;
    if (row >= rows) return;
    const float* A = (mode == 0) ? Aext : g_X;
    const float* p = A + (size_t)row * 512;
    float s = 0.f;
#pragma unroll
    for (int c = 0; c < 4; c++) {
        float4 v = *(const float4*)(p + c * 128 + lane * 4);
        s += v.x * v.x + v.y * v.y + v.z * v.z + v.w * v.w;
    }
#pragma unroll
    for (int o = 16; o; o >>= 1) s += __shfl_xor_sync(0xffffffffu, s, o);
    if (lane == 0) {
        if (mode == 0) g_enorm[row] = s;
        else           g_xnorm[row] = s;
    }
}

// ---------------- GEMM 1&2: C = A @ B + bias (NN), f32x2 inner ------------
__global__ __launch_bounds__(256) void sgemm_bias_kernel(
    const float* __restrict__ Aext, const float* __restrict__ B,
    const float* __restrict__ bias, int aflag, int cflag,
    int M, int N, int K)
{
    __shared__ __align__(16) float As[8][128];
    __shared__ __align__(16) ull   Bd[8][16][16];   // [kk][jj][t15] dup pairs
    const int tid  = threadIdx.x;
    const int bm   = blockIdx.y * 128;
    const int bn   = blockIdx.x * 128;
    const int arow = tid >> 1, acol = (tid & 1) * 4;
    const int brow = tid >> 5, bcol = (tid & 31) * 4;
    const int trow = (tid >> 4) * 8, t15 = tid & 15, tcol = t15 * 8;

    const float* A = aflag ? g_X : Aext;
    float*       C = cflag ? g_Z : g_X;

    ull acc2[4][8];
#pragma unroll
    for (int ip = 0; ip < 4; ip++)
#pragma unroll
        for (int j = 0; j < 8; j++) acc2[ip][j] = 0ull;

    const float* Ap = A + (size_t)(bm + arow) * K + acol;
    const float* Bp = B + (size_t)brow * N + bn + bcol;

    for (int k0 = 0; k0 < K; k0 += 8) {
        float4 av = *(const float4*)(Ap + k0);
        As[acol + 0][arow] = av.x; As[acol + 1][arow] = av.y;
        As[acol + 2][arow] = av.z; As[acol + 3][arow] = av.w;
        float4 bv = *(const float4*)(Bp + (size_t)k0 * N);
        Bd[brow][(bcol + 0) & 7][(bcol + 0) >> 3] = dup2(bv.x);
        Bd[brow][(bcol + 1) & 7][(bcol + 1) >> 3] = dup2(bv.y);
        Bd[brow][(bcol + 2) & 7][(bcol + 2) >> 3] = dup2(bv.z);
        Bd[brow][(bcol + 3) & 7][(bcol + 3) >> 3] = dup2(bv.w);
        __syncthreads();
#pragma unroll
        for (int kk = 0; kk < 8; kk++) {
            U4 a0, a1;
            a0.f = *(const float4*)&As[kk][trow];
            a1.f = *(const float4*)&As[kk][trow + 4];
            ull ap[4] = {a0.u[0], a0.u[1], a1.u[0], a1.u[1]};
            ull bp[8];
#pragma unroll
            for (int jj = 0; jj < 8; jj++) bp[jj] = Bd[kk][jj][t15];
#pragma unroll
            for (int ip = 0; ip < 4; ip++)
#pragma unroll
                for (int jj = 0; jj < 8; jj++)
                    fma2(acc2[ip][jj], ap[ip], bp[jj]);
        }
        __syncthreads();
    }

    float accf[8][8];
#pragma unroll
    for (int ip = 0; ip < 4; ip++)
#pragma unroll
        for (int jj = 0; jj < 8; jj++) {
            float2 p = up2(acc2[ip][jj]);
            accf[2 * ip][jj] = p.x; accf[2 * ip + 1][jj] = p.y;
        }

    float4 bv0 = *(const float4*)(bias + bn + tcol);
    float4 bv1 = *(const float4*)(bias + bn + tcol + 4);
    float bb[8] = {bv0.x, bv0.y, bv0.z, bv0.w, bv1.x, bv1.y, bv1.z, bv1.w};
#pragma unroll
    for (int i = 0; i < 8; i++) {
        size_t row = (size_t)(bm + trow + i);
        float* cp = C + row * N + bn + tcol;
        float4 v0 = {accf[i][0] + bb[0], accf[i][1] + bb[1], accf[i][2] + bb[2], accf[i][3] + bb[3]};
        float4 v1 = {accf[i][4] + bb[4], accf[i][5] + bb[5], accf[i][6] + bb[6], accf[i][7] + bb[7]};
        *(float4*)cp       = v0;
        *(float4*)(cp + 4) = v1;
    }
}

// ------- GEMM 3: dots = g_X @ E^T, prob epilogue -> g_Z (f32x2 inner) ------
__global__ __launch_bounds__(256) void gemm_prob_kernel(const float* __restrict__ E)
{
    __shared__ __align__(16) float As[8][128];
    __shared__ __align__(16) ull   Bd[8][16][16];
    const int tid  = threadIdx.x;
    const int bm   = blockIdx.y * 128;
    const int bn   = blockIdx.x * 128;
    const int arow = tid >> 1, acol = (tid & 1) * 4;
    const int trow = (tid >> 4) * 8, t15 = tid & 15, tcol = t15 * 8;

    ull acc2[4][8];
#pragma unroll
    for (int ip = 0; ip < 4; ip++)
#pragma unroll
        for (int j = 0; j < 8; j++) acc2[ip][j] = 0ull;

    const float* Ap = g_X + (size_t)(bm + arow) * DIM + acol;
    const float* Ep = E   + (size_t)(bn + arow) * DIM + acol;

    for (int k0 = 0; k0 < DIM; k0 += 8) {
        float4 av = *(const float4*)(Ap + k0);
        As[acol + 0][arow] = av.x; As[acol + 1][arow] = av.y;
        As[acol + 2][arow] = av.z; As[acol + 3][arow] = av.w;
        float4 ev = *(const float4*)(Ep + k0);
        Bd[acol + 0][arow & 7][arow >> 3] = dup2(ev.x);
        Bd[acol + 1][arow & 7][arow >> 3] = dup2(ev.y);
        Bd[acol + 2][arow & 7][arow >> 3] = dup2(ev.z);
        Bd[acol + 3][arow & 7][arow >> 3] = dup2(ev.w);
        __syncthreads();
#pragma unroll
        for (int kk = 0; kk < 8; kk++) {
            U4 a0, a1;
            a0.f = *(const float4*)&As[kk][trow];
            a1.f = *(const float4*)&As[kk][trow + 4];
            ull ap[4] = {a0.u[0], a0.u[1], a1.u[0], a1.u[1]};
            ull bp[8];
#pragma unroll
            for (int jj = 0; jj < 8; jj++) bp[jj] = Bd[kk][jj][t15];
#pragma unroll
            for (int ip = 0; ip < 4; ip++)
#pragma unroll
                for (int jj = 0; jj < 8; jj++)
                    fma2(acc2[ip][jj], ap[ip], bp[jj]);
        }
        __syncthreads();
    }

    float accf[8][8];
#pragma unroll
    for (int ip = 0; ip < 4; ip++)
#pragma unroll
        for (int jj = 0; jj < 8; jj++) {
            float2 p = up2(acc2[ip][jj]);
            accf[2 * ip][jj] = p.x; accf[2 * ip + 1][jj] = p.y;
        }

    float4 e0 = *(const float4*)(g_enorm + bn + tcol);
    float4 e1 = *(const float4*)(g_enorm + bn + tcol + 4);
    float er[8] = {e0.x, e0.y, e0.z, e0.w, e1.x, e1.y, e1.z, e1.w};
#pragma unroll
    for (int i = 0; i < 8; i++) {
        size_t row = (size_t)(bm + trow + i);
        float xn = g_xnorm[row];
        float* zp = g_Z + row * KCB + bn + tcol;
        float4 z0 = *(const float4*)zp;
        float4 z1 = *(const float4*)(zp + 4);
        float zr[8] = {z0.x, z0.y, z0.z, z0.w, z1.x, z1.y, z1.z, z1.w};
        float pr[8];
#pragma unroll
        for (int j = 0; j < 8; j++) {
            float dist = xn + er[j] - 2.f * accf[i][j];
            float dd   = dist * (1.f / 400.f);
            float sm   = expf(-2.f * zr[j]);
            pr[j]      = expf(zr[j] - 0.5f * dd * sm);
        }
        float4 p0 = {pr[0], pr[1], pr[2], pr[3]};
        float4 p1 = {pr[4], pr[5], pr[6], pr[7]};
        *(float4*)zp       = p0;
        *(float4*)(zp + 4) = p1;
    }
}

// --- normalize (R1 verbatim) ---
__global__ __launch_bounds__(256) void normalize_kernel(float* __restrict__ Pout)
{
    __shared__ float scol[512];
    int tid = threadIdx.x, lane = tid & 31, warp = tid >> 5;
    for (int i = tid; i < 512; i += 256) scol[i] = 0.f;
    __syncthreads();

    int row0 = blockIdx.x * 32 + warp * 4;
    float local[16];
#pragma unroll
    for (int i = 0; i < 16; i++) local[i] = 0.f;

    for (int r = 0; r < 4; r++) {
        size_t base = (size_t)(row0 + r) * KCB;
        float4 v[4];
        float s = 0.f;
#pragma unroll
        for (int c = 0; c < 4; c++) {
            v[c] = *(const float4*)(g_Z + base + c * 128 + lane * 4);
            s += v[c].x + v[c].y + v[c].z + v[c].w;
        }
#pragma unroll
        for (int o = 16; o; o >>= 1) s += __shfl_xor_sync(0xffffffffu, s, o);
        float inv = 1.f / s;
#pragma unroll
        for (int c = 0; c < 4; c++) {
            v[c].x *= inv; v[c].y *= inv; v[c].z *= inv; v[c].w *= inv;
            *(float4*)(g_Z + base + c * 128 + lane * 4) = v[c];
            float2 lo = {v[c].x, v[c].y};
            float2 hi = {v[c].z, v[c].w};
            *(float2*)(Pout + base + c * 128 + lane * 4)     = lo;
            *(float2*)(Pout + base + c * 128 + lane * 4 + 2) = hi;
            local[c * 4 + 0] += v[c].x; local[c * 4 + 1] += v[c].y;
            local[c * 4 + 2] += v[c].z; local[c * 4 + 3] += v[c].w;
        }
    }
#pragma unroll
    for (int c = 0; c < 4; c++)
#pragma unroll
        for (int t = 0; t < 4; t++)
            atomicAdd(&scol[c * 128 + lane * 4 + t], local[c * 4 + t]);
    __syncthreads();
    for (int i = tid; i < 512; i += 256) atomicAdd(&g_colsum[i], scol[i]);
}

// ---- GEMM 4: quantized = probs @ E ; qst + SSE (f32x2 inner) --------------
__global__ __launch_bounds__(256) void gemm_quant_kernel(
    const float* __restrict__ E, const float* __restrict__ IN,
    float* __restrict__ Q)
{
    __shared__ __align__(16) float As[8][128];
    __shared__ __align__(16) ull   Bd[8][16][16];
    __shared__ double sred[256];
    const int tid  = threadIdx.x;
    const int bm   = blockIdx.y * 128;
    const int bn   = blockIdx.x * 128;
    const int arow = tid >> 1, acol = (tid & 1) * 4;
    const int brow = tid >> 5, bcol = (tid & 31) * 4;
    const int trow = (tid >> 4) * 8, t15 = tid & 15, tcol = t15 * 8;

    ull acc2[4][8];
#pragma unroll
    for (int ip = 0; ip < 4; ip++)
#pragma unroll
        for (int j = 0; j < 8; j++) acc2[ip][j] = 0ull;

    const float* Ap = g_Z + (size_t)(bm + arow) * KCB + acol;
    const float* Bp = E   + (size_t)brow * DIM + bn + bcol;

    for (int k0 = 0; k0 < KCB; k0 += 8) {
        float4 av = *(const float4*)(Ap + k0);
        As[acol + 0][arow] = av.x; As[acol + 1][arow] = av.y;
        As[acol + 2][arow] = av.z; As[acol + 3][arow] = av.w;
        float4 bv = *(const float4*)(Bp + (size_t)k0 * DIM);
        Bd[brow][(bcol + 0) & 7][(bcol + 0) >> 3] = dup2(bv.x);
        Bd[brow][(bcol + 1) & 7][(bcol + 1) >> 3] = dup2(bv.y);
        Bd[brow][(bcol + 2) & 7][(bcol + 2) >> 3] = dup2(bv.z);
        Bd[brow][(bcol + 3) & 7][(bcol + 3) >> 3] = dup2(bv.w);
        __syncthreads();
#pragma unroll
        for (int kk = 0; kk < 8; kk++) {
            U4 a0, a1;
            a0.f = *(const float4*)&As[kk][trow];
            a1.f = *(const float4*)&As[kk][trow + 4];
            ull ap[4] = {a0.u[0], a0.u[1], a1.u[0], a1.u[1]};
            ull bp[8];
#pragma unroll
            for (int jj = 0; jj < 8; jj++) bp[jj] = Bd[kk][jj][t15];
#pragma unroll
            for (int ip = 0; ip < 4; ip++)
#pragma unroll
                for (int jj = 0; jj < 8; jj++)
                    fma2(acc2[ip][jj], ap[ip], bp[jj]);
        }
        __syncthreads();
    }

    float accf[8][8];
#pragma unroll
    for (int ip = 0; ip < 4; ip++)
#pragma unroll
        for (int jj = 0; jj < 8; jj++) {
            float2 p = up2(acc2[ip][jj]);
            accf[2 * ip][jj] = p.x; accf[2 * ip + 1][jj] = p.y;
        }

    double lsse = 0.0;
#pragma unroll
    for (int i = 0; i < 8; i++) {
        size_t row = (size_t)(bm + trow + i);
        const float* inp = IN + row * DIM + bn + tcol;
        float* qp = Q + row * DIM + bn + tcol;
        float4 in0 = *(const float4*)inp;
        float4 in1 = *(const float4*)(inp + 4);
        float inr[8] = {in0.x, in0.y, in0.z, in0.w, in1.x, in1.y, in1.z, in1.w};
#pragma unroll
        for (int j = 0; j < 8; j++) {
            float q = accf[i][j];
            float diff = q - inr[j];
            lsse += (double)(diff * diff);
            qp[j] = inr[j] + (q - inr[j]);
        }
    }
    sred[tid] = lsse;
    __syncthreads();
    for (int s = 128; s; s >>= 1) {
        if (tid < s) sred[tid] += sred[tid + s];
        __syncthreads();
    }
    if (tid == 0) atomicAdd(&g_sse, sred[0]);
}

// ---------------- finalize (R1 verbatim) ----------------
__global__ void finalize_kernel(float* __restrict__ loss_ptr,
                                float* __restrict__ ppl_ptr)
{
    __shared__ float sred[512];
    int tid = threadIdx.x;
    float avg = g_colsum[tid] * (1.f / (float)NTOK);
    sred[tid] = avg * logf(avg + 1e-10f);
    __syncthreads();
    for (int s = 256; s; s >>= 1) {
        if (tid < s) sred[tid] += sred[tid + s];
        __syncthreads();
    }
    if (tid == 0) {
        *ppl_ptr  = expf(-sred[0]);
        *loss_ptr = (float)(1.25 * g_sse * (1.0 / ((double)NTOK * (double)DIM)));
    }
}

extern "C" void kernel_launch(void* const* d_in, const int* in_sizes, int n_in,
                              void* d_out, int out_size)
{
    (void)in_sizes; (void)n_in; (void)out_size;
    const float* x   = (const float*)d_in[0];
    const float* mW  = (const float*)d_in[1];
    const float* mb  = (const float*)d_in[2];
    const float* lW  = (const float*)d_in[3];
    const float* lb  = (const float*)d_in[4];
    const float* emb = (const float*)d_in[5];

    float* o         = (float*)d_out;
    float* loss_ptr  = o;
    float* q_ptr     = o + 1;
    float* ppl_ptr   = o + 1 + NDsz;
    float* probs_ptr = o + 2 + NDsz;

    dim3 g4(KCB / 128, NTOK / 128);

    init_kernel<<<1, 512>>>();
    rownorm2_kernel<<<KCB / 8, 256>>>(emb, 0, KCB);
    sgemm_bias_kernel<<<g4, 256>>>(x, mW, mb, 0, 0, NTOK, DIM, DIM);
    rownorm2_kernel<<<NTOK / 8, 256>>>(nullptr, 1, NTOK);
    sgemm_bias_kernel<<<g4, 256>>>(nullptr, lW, lb, 1, 1, NTOK, KCB, DIM);
    gemm_prob_kernel<<<g4, 256>>>(emb);
    normalize_kernel<<<NTOK / 32, 256>>>(probs_ptr);
    gemm_quant_kernel<<<dim3(DIM / 128, NTOK / 128), 256>>>(emb, x, q_ptr);
    finalize_kernel<<<1, 512>>>(loss_ptr, ppl_ptr);
}

// round 11
// speedup vs baseline: 1.0992x; 1.0992x over previous
#include <cuda_runtime.h>
#include <stdint.h>
#include <math.h>

#define NTOK 65536
#define DIM  512
#define KCB  512
#define NDsz ((size_t)NTOK * (size_t)DIM)
typedef unsigned long long ull;

// ---- scratch (R1-proven fp32 flow) ----
__device__ float  g_X[NDsz];
__device__ float  g_Z[NDsz];
__device__ float  g_xnorm[NTOK];
__device__ float  g_enorm[KCB];
__device__ float  g_colsum[KCB];
__device__ double g_sse;

// ---- packed fp32x2 helpers ----
__device__ __forceinline__ void fma2(ull& c, ull a, ull b) {
    asm("fma.rn.f32x2 %0, %1, %2, %0;" : "+l"(c) : "l"(a), "l"(b));
}
__device__ __forceinline__ ull dup2(float v) {
    ull r;
    asm("mov.b64 %0, {%1, %1};" : "=l"(r) : "f"(v));
    return r;
}
__device__ __forceinline__ float2 up2(ull v) {
    float2 f;
    asm("mov.b64 {%0, %1}, %2;" : "=f"(f.x), "=f"(f.y) : "l"(v));
    return f;
}
union U4 { float4 f; ull u[2]; };

// ---------------- init (R1 verbatim) ----------------
__global__ void init_kernel() {
    int t = threadIdx.x;
    if (t < KCB) g_colsum[t] = 0.f;
    if (t == 0)  g_sse = 0.0;
}

// ---- row norms (R1 verbatim) ----
__global__ void rownorm2_kernel(const float* __restrict__ Aext, int mode, int rows) {
    int lane = threadIdx.x & 31;
    int warp = threadIdx.x >> 5;
    int row  = blockIdx.x * 8 + warp;
    if (row >= rows) return;
    const float* A = (mode == 0) ? Aext : g_X;
    const float* p = A + (size_t)row * 512;
    float s = 0.f;
#pragma unroll
    for (int c = 0; c < 4; c++) {
        float4 v = *(const float4*)(p + c * 128 + lane * 4);
        s += v.x * v.x + v.y * v.y + v.z * v.z + v.w * v.w;
    }
#pragma unroll
    for (int o = 16; o; o >>= 1) s += __shfl_xor_sync(0xffffffffu, s, o);
    if (lane == 0) {
        if (mode == 0) g_enorm[row] = s;
        else           g_xnorm[row] = s;
    }
}

// ---------------- GEMM 1&2: C = A @ B + bias (R1 layout, FFMA2 inner) -----
__global__ __launch_bounds__(256) void sgemm_bias_kernel(
    const float* __restrict__ Aext, const float* __restrict__ B,
    const float* __restrict__ bias, int aflag, int cflag,
    int M, int N, int K)
{
    __shared__ __align__(16) float As[8][128];
    __shared__ __align__(16) float Bs[8][128];
    const int tid  = threadIdx.x;
    const int bm   = blockIdx.y * 128;
    const int bn   = blockIdx.x * 128;
    const int arow = tid >> 1, acol = (tid & 1) * 4;
    const int brow = tid >> 5, bcol = (tid & 31) * 4;
    const int trow = (tid >> 4) * 8, tcol = (tid & 15) * 8;

    const float* A = aflag ? g_X : Aext;
    float*       C = cflag ? g_Z : g_X;

    ull acc2[4][8];   // row-pairs (trow+2ip, trow+2ip+1) x 8 cols
#pragma unroll
    for (int ip = 0; ip < 4; ip++)
#pragma unroll
        for (int j = 0; j < 8; j++) acc2[ip][j] = 0ull;

    const float* Ap = A + (size_t)(bm + arow) * K + acol;
    const float* Bp = B + (size_t)brow * N + bn + bcol;

    for (int k0 = 0; k0 < K; k0 += 8) {
        float4 av = *(const float4*)(Ap + k0);
        As[acol + 0][arow] = av.x; As[acol + 1][arow] = av.y;
        As[acol + 2][arow] = av.z; As[acol + 3][arow] = av.w;
        *(float4*)&Bs[brow][bcol] = *(const float4*)(Bp + (size_t)k0 * N);
        __syncthreads();
#pragma unroll
        for (int kk = 0; kk < 8; kk++) {
            U4 a0, a1;
            a0.f = *(const float4*)&As[kk][trow];      // rows (trow..trow+3) as 2 pairs
            a1.f = *(const float4*)&As[kk][trow + 4];
            ull ap[4] = {a0.u[0], a0.u[1], a1.u[0], a1.u[1]};
            float4 b0 = *(const float4*)&Bs[kk][tcol];
            float4 b1 = *(const float4*)&Bs[kk][tcol + 4];
            ull bp[8] = {dup2(b0.x), dup2(b0.y), dup2(b0.z), dup2(b0.w),
                         dup2(b1.x), dup2(b1.y), dup2(b1.z), dup2(b1.w)};
#pragma unroll
            for (int ip = 0; ip < 4; ip++)
#pragma unroll
                for (int j = 0; j < 8; j++)
                    fma2(acc2[ip][j], ap[ip], bp[j]);
        }
        __syncthreads();
    }

    float accf[8][8];
#pragma unroll
    for (int ip = 0; ip < 4; ip++)
#pragma unroll
        for (int j = 0; j < 8; j++) {
            float2 p = up2(acc2[ip][j]);
            accf[2 * ip][j] = p.x; accf[2 * ip + 1][j] = p.y;
        }

    float4 bv0 = *(const float4*)(bias + bn + tcol);
    float4 bv1 = *(const float4*)(bias + bn + tcol + 4);
    float bb[8] = {bv0.x, bv0.y, bv0.z, bv0.w, bv1.x, bv1.y, bv1.z, bv1.w};
#pragma unroll
    for (int i = 0; i < 8; i++) {
        size_t row = (size_t)(bm + trow + i);
        float* cp = C + row * N + bn + tcol;
        float4 v0 = {accf[i][0] + bb[0], accf[i][1] + bb[1], accf[i][2] + bb[2], accf[i][3] + bb[3]};
        float4 v1 = {accf[i][4] + bb[4], accf[i][5] + bb[5], accf[i][6] + bb[6], accf[i][7] + bb[7]};
        *(float4*)cp       = v0;
        *(float4*)(cp + 4) = v1;
    }
}

// ------- GEMM 3: dots = g_X @ E^T, prob epilogue (R1 layout, FFMA2) -------
__global__ __launch_bounds__(256) void gemm_prob_kernel(const float* __restrict__ E)
{
    __shared__ __align__(16) float As[8][128];
    __shared__ __align__(16) float Bs[8][128];
    const int tid  = threadIdx.x;
    const int bm   = blockIdx.y * 128;
    const int bn   = blockIdx.x * 128;
    const int arow = tid >> 1, acol = (tid & 1) * 4;
    const int trow = (tid >> 4) * 8, tcol = (tid & 15) * 8;

    ull acc2[4][8];
#pragma unroll
    for (int ip = 0; ip < 4; ip++)
#pragma unroll
        for (int j = 0; j < 8; j++) acc2[ip][j] = 0ull;

    const float* Ap = g_X + (size_t)(bm + arow) * DIM + acol;
    const float* Ep = E   + (size_t)(bn + arow) * DIM + acol;

    for (int k0 = 0; k0 < DIM; k0 += 8) {
        float4 av = *(const float4*)(Ap + k0);
        As[acol + 0][arow] = av.x; As[acol + 1][arow] = av.y;
        As[acol + 2][arow] = av.z; As[acol + 3][arow] = av.w;
        float4 ev = *(const float4*)(Ep + k0);
        Bs[acol + 0][arow] = ev.x; Bs[acol + 1][arow] = ev.y;
        Bs[acol + 2][arow] = ev.z; Bs[acol + 3][arow] = ev.w;
        __syncthreads();
#pragma unroll
        for (int kk = 0; kk < 8; kk++) {
            U4 a0, a1;
            a0.f = *(const float4*)&As[kk][trow];
            a1.f = *(const float4*)&As[kk][trow + 4];
            ull ap[4] = {a0.u[0], a0.u[1], a1.u[0], a1.u[1]};
            float4 b0 = *(const float4*)&Bs[kk][tcol];
            float4 b1 = *(const float4*)&Bs[kk][tcol + 4];
            ull bp[8] = {dup2(b0.x), dup2(b0.y), dup2(b0.z), dup2(b0.w),
                         dup2(b1.x), dup2(b1.y), dup2(b1.z), dup2(b1.w)};
#pragma unroll
            for (int ip = 0; ip < 4; ip++)
#pragma unroll
                for (int j = 0; j < 8; j++)
                    fma2(acc2[ip][j], ap[ip], bp[j]);
        }
        __syncthreads();
    }

    float accf[8][8];
#pragma unroll
    for (int ip = 0; ip < 4; ip++)
#pragma unroll
        for (int j = 0; j < 8; j++) {
            float2 p = up2(acc2[ip][j]);
            accf[2 * ip][j] = p.x; accf[2 * ip + 1][j] = p.y;
        }

    float4 e0 = *(const float4*)(g_enorm + bn + tcol);
    float4 e1 = *(const float4*)(g_enorm + bn + tcol + 4);
    float er[8] = {e0.x, e0.y, e0.z, e0.w, e1.x, e1.y, e1.z, e1.w};
#pragma unroll
    for (int i = 0; i < 8; i++) {
        size_t row = (size_t)(bm + trow + i);
        float xn = g_xnorm[row];
        float* zp = g_Z + row * KCB + bn + tcol;
        float4 z0 = *(const float4*)zp;
        float4 z1 = *(const float4*)(zp + 4);
        float zr[8] = {z0.x, z0.y, z0.z, z0.w, z1.x, z1.y, z1.z, z1.w};
        float pr[8];
#pragma unroll
        for (int j = 0; j < 8; j++) {
            float dist = xn + er[j] - 2.f * accf[i][j];
            float dd   = dist * (1.f / 400.f);
            float sm   = expf(-2.f * zr[j]);
            pr[j]      = expf(zr[j] - 0.5f * dd * sm);
        }
        float4 p0 = {pr[0], pr[1], pr[2], pr[3]};
        float4 p1 = {pr[4], pr[5], pr[6], pr[7]};
        *(float4*)zp       = p0;
        *(float4*)(zp + 4) = p1;
    }
}

// --- normalize (R1 verbatim) ---
__global__ __launch_bounds__(256) void normalize_kernel(float* __restrict__ Pout)
{
    __shared__ float scol[512];
    int tid = threadIdx.x, lane = tid & 31, warp = tid >> 5;
    for (int i = tid; i < 512; i += 256) scol[i] = 0.f;
    __syncthreads();

    int row0 = blockIdx.x * 32 + warp * 4;
    float local[16];
#pragma unroll
    for (int i = 0; i < 16; i++) local[i] = 0.f;

    for (int r = 0; r < 4; r++) {
        size_t base = (size_t)(row0 + r) * KCB;
        float4 v[4];
        float s = 0.f;
#pragma unroll
        for (int c = 0; c < 4; c++) {
            v[c] = *(const float4*)(g_Z + base + c * 128 + lane * 4);
            s += v[c].x + v[c].y + v[c].z + v[c].w;
        }
#pragma unroll
        for (int o = 16; o; o >>= 1) s += __shfl_xor_sync(0xffffffffu, s, o);
        float inv = 1.f / s;
#pragma unroll
        for (int c = 0; c < 4; c++) {
            v[c].x *= inv; v[c].y *= inv; v[c].z *= inv; v[c].w *= inv;
            *(float4*)(g_Z + base + c * 128 + lane * 4) = v[c];
            float2 lo = {v[c].x, v[c].y};
            float2 hi = {v[c].z, v[c].w};
            *(float2*)(Pout + base + c * 128 + lane * 4)     = lo;
            *(float2*)(Pout + base + c * 128 + lane * 4 + 2) = hi;
            local[c * 4 + 0] += v[c].x; local[c * 4 + 1] += v[c].y;
            local[c * 4 + 2] += v[c].z; local[c * 4 + 3] += v[c].w;
        }
    }
#pragma unroll
    for (int c = 0; c < 4; c++)
#pragma unroll
        for (int t = 0; t < 4; t++)
            atomicAdd(&scol[c * 128 + lane * 4 + t], local[c * 4 + t]);
    __syncthreads();
    for (int i = tid; i < 512; i += 256) atomicAdd(&g_colsum[i], scol[i]);
}

// ---- GEMM 4: quantized = probs @ E ; qst + SSE (R1 layout, FFMA2) --------
__global__ __launch_bounds__(256) void gemm_quant_kernel(
    const float* __restrict__ E, const float* __restrict__ IN,
    float* __restrict__ Q)
{
    __shared__ __align__(16) float As[8][128];
    __shared__ __align__(16) float Bs[8][128];
    __shared__ double sred[256];
    const int tid  = threadIdx.x;
    const int bm   = blockIdx.y * 128;
    const int bn   = blockIdx.x * 128;
    const int arow = tid >> 1, acol = (tid & 1) * 4;
    const int brow = tid >> 5, bcol = (tid & 31) * 4;
    const int trow = (tid >> 4) * 8, tcol = (tid & 15) * 8;

    ull acc2[4][8];
#pragma unroll
    for (int ip = 0; ip < 4; ip++)
#pragma unroll
        for (int j = 0; j < 8; j++) acc2[ip][j] = 0ull;

    const float* Ap = g_Z + (size_t)(bm + arow) * KCB + acol;
    const float* Bp = E   + (size_t)brow * DIM + bn + bcol;

    for (int k0 = 0; k0 < KCB; k0 += 8) {
        float4 av = *(const float4*)(Ap + k0);
        As[acol + 0][arow] = av.x; As[acol + 1][arow] = av.y;
        As[acol + 2][arow] = av.z; As[acol + 3][arow] = av.w;
        *(float4*)&Bs[brow][bcol] = *(const float4*)(Bp + (size_t)k0 * DIM);
        __syncthreads();
#pragma unroll
        for (int kk = 0; kk < 8; kk++) {
            U4 a0, a1;
            a0.f = *(const float4*)&As[kk][trow];
            a1.f = *(const float4*)&As[kk][trow + 4];
            ull ap[4] = {a0.u[0], a0.u[1], a1.u[0], a1.u[1]};
            float4 b0 = *(const float4*)&Bs[kk][tcol];
            float4 b1 = *(const float4*)&Bs[kk][tcol + 4];
            ull bp[8] = {dup2(b0.x), dup2(b0.y), dup2(b0.z), dup2(b0.w),
                         dup2(b1.x), dup2(b1.y), dup2(b1.z), dup2(b1.w)};
#pragma unroll
            for (int ip = 0; ip < 4; ip++)
#pragma unroll
                for (int j = 0; j < 8; j++)
                    fma2(acc2[ip][j], ap[ip], bp[j]);
        }
        __syncthreads();
    }

    float accf[8][8];
#pragma unroll
    for (int ip = 0; ip < 4; ip++)
#pragma unroll
        for (int j = 0; j < 8; j++) {
            float2 p = up2(acc2[ip][j]);
            accf[2 * ip][j] = p.x; accf[2 * ip + 1][j] = p.y;
        }

    double lsse = 0.0;
#pragma unroll
    for (int i = 0; i < 8; i++) {
        size_t row = (size_t)(bm + trow + i);
        const float* inp = IN + row * DIM + bn + tcol;
        float* qp = Q + row * DIM + bn + tcol;
        float4 in0 = *(const float4*)inp;
        float4 in1 = *(const float4*)(inp + 4);
        float inr[8] = {in0.x, in0.y, in0.z, in0.w, in1.x, in1.y, in1.z, in1.w};
#pragma unroll
        for (int j = 0; j < 8; j++) {
            float q = accf[i][j];
            float diff = q - inr[j];
            lsse += (double)(diff * diff);
            qp[j] = inr[j] + (q - inr[j]);
        }
    }
    sred[tid] = lsse;
    __syncthreads();
    for (int s = 128; s; s >>= 1) {
        if (tid < s) sred[tid] += sred[tid + s];
        __syncthreads();
    }
    if (tid == 0) atomicAdd(&g_sse, sred[0]);
}

// ---------------- finalize (R1 verbatim) ----------------
__global__ void finalize_kernel(float* __restrict__ loss_ptr,
                                float* __restrict__ ppl_ptr)
{
    __shared__ float sred[512];
    int tid = threadIdx.x;
    float avg = g_colsum[tid] * (1.f / (float)NTOK);
    sred[tid] = avg * logf(avg + 1e-10f);
    __syncthreads();
    for (int s = 256; s; s >>= 1) {
        if (tid < s) sred[tid] += sred[tid + s];
        __syncthreads();
    }
    if (tid == 0) {
        *ppl_ptr  = expf(-sred[0]);
        *loss_ptr = (float)(1.25 * g_sse * (1.0 / ((double)NTOK * (double)DIM)));
    }
}

extern "C" void kernel_launch(void* const* d_in, const int* in_sizes, int n_in,
                              void* d_out, int out_size)
{
    (void)in_sizes; (void)n_in; (void)out_size;
    const float* x   = (const float*)d_in[0];
    const float* mW  = (const float*)d_in[1];
    const float* mb  = (const float*)d_in[2];
    const float* lW  = (const float*)d_in[3];
    const float* lb  = (const float*)d_in[4];
    const float* emb = (const float*)d_in[5];

    float* o         = (float*)d_out;
    float* loss_ptr  = o;
    float* q_ptr     = o + 1;
    float* ppl_ptr   = o + 1 + NDsz;
    float* probs_ptr = o + 2 + NDsz;

    dim3 g4(KCB / 128, NTOK / 128);

    init_kernel<<<1, 512>>>();
    rownorm2_kernel<<<KCB / 8, 256>>>(emb, 0, KCB);
    sgemm_bias_kernel<<<g4, 256>>>(x, mW, mb, 0, 0, NTOK, DIM, DIM);
    rownorm2_kernel<<<NTOK / 8, 256>>>(nullptr, 1, NTOK);
    sgemm_bias_kernel<<<g4, 256>>>(nullptr, lW, lb, 1, 1, NTOK, KCB, DIM);
    gemm_prob_kernel<<<g4, 256>>>(emb);
    normalize_kernel<<<NTOK / 32, 256>>>(probs_ptr);
    gemm_quant_kernel<<<dim3(DIM / 128, NTOK / 128), 256>>>(emb, x, q_ptr);
    finalize_kernel<<<1, 512>>>(loss_ptr, ppl_ptr);
}

// round 13
// speedup vs baseline: 1.1029x; 1.0034x over previous
#include <cuda_runtime.h>
#include <stdint.h>
#include <math.h>

#define NTOK 65536
#define DIM  512
#define KCB  512
#define NDsz ((size_t)NTOK * (size_t)DIM)
typedef unsigned long long ull;

// ---- scratch ----
__device__ float  g_X[NDsz];
__device__ float  g_Z[NDsz];      // z -> unnormalized probs
__device__ float  g_xnorm[NTOK];
__device__ float  g_rinv[NTOK];   // 1 / row-sum of unnormalized probs
__device__ float  g_enorm[KCB];
__device__ float  g_colsum[KCB];
__device__ double g_sse;

// ---- packed fp32x2 helpers (R11) ----
__device__ __forceinline__ void fma2(ull& c, ull a, ull b) {
    asm("fma.rn.f32x2 %0, %1, %2, %0;" : "+l"(c) : "l"(a), "l"(b));
}
__device__ __forceinline__ ull dup2(float v) {
    ull r;
    asm("mov.b64 %0, {%1, %1};" : "=l"(r) : "f"(v));
    return r;
}
__device__ __forceinline__ float2 up2(ull v) {
    float2 f;
    asm("mov.b64 {%0, %1}, %2;" : "=f"(f.x), "=f"(f.y) : "l"(v));
    return f;
}
union U4 { float4 f; ull u[2]; };

// ---------------- init ----------------
__global__ void init_kernel() {
    int i = blockIdx.x * blockDim.x + threadIdx.x;
    if (i < NTOK) g_xnorm[i] = 0.f;
    if (i < KCB)  g_colsum[i] = 0.f;
    if (i == 0)   g_sse = 0.0;
}

// ---- embedding row norms only ----
__global__ void rownorm2_kernel(const float* __restrict__ Aext) {
    int lane = threadIdx.x & 31;
    int warp = threadIdx.x >> 5;
    int row  = blockIdx.x * 8 + warp;
    if (row >= KCB) return;
    const float* p = Aext + (size_t)row * 512;
    float s = 0.f;
#pragma unroll
    for (int c = 0; c < 4; c++) {
        float4 v = *(const float4*)(p + c * 128 + lane * 4);
        s += v.x * v.x + v.y * v.y + v.z * v.z + v.w * v.w;
    }
#pragma unroll
    for (int o = 16; o; o >>= 1) s += __shfl_xor_sync(0xffffffffu, s, o);
    if (lane == 0) g_enorm[row] = s;
}

// ---------------- GEMM 1&2: C = A @ B + bias (FFMA2 inner) ----------------
// cflag 0: C=g_X + fused xnorm atomics ; cflag 1: C=g_Z
__global__ __launch_bounds__(256) void sgemm_bias_kernel(
    const float* __restrict__ Aext, const float* __restrict__ B,
    const float* __restrict__ bias, int aflag, int cflag,
    int M, int N, int K)
{
    __shared__ __align__(16) float As[8][128];
    __shared__ __align__(16) float Bs[8][128];
    const int tid  = threadIdx.x;
    const int bm   = blockIdx.y * 128;
    const int bn   = blockIdx.x * 128;
    const int arow = tid >> 1, acol = (tid & 1) * 4;
    const int brow = tid >> 5, bcol = (tid & 31) * 4;
    const int trow = (tid >> 4) * 8, tcol = (tid & 15) * 8;

    const float* A = aflag ? g_X : Aext;
    float*       C = cflag ? g_Z : g_X;

    ull acc2[4][8];
#pragma unroll
    for (int ip = 0; ip < 4; ip++)
#pragma unroll
        for (int j = 0; j < 8; j++) acc2[ip][j] = 0ull;

    const float* Ap = A + (size_t)(bm + arow) * K + acol;
    const float* Bp = B + (size_t)brow * N + bn + bcol;

    for (int k0 = 0; k0 < K; k0 += 8) {
        float4 av = *(const float4*)(Ap + k0);
        As[acol + 0][arow] = av.x; As[acol + 1][arow] = av.y;
        As[acol + 2][arow] = av.z; As[acol + 3][arow] = av.w;
        *(float4*)&Bs[brow][bcol] = *(const float4*)(Bp + (size_t)k0 * N);
        __syncthreads();
#pragma unroll
        for (int kk = 0; kk < 8; kk++) {
            U4 a0, a1;
            a0.f = *(const float4*)&As[kk][trow];
            a1.f = *(const float4*)&As[kk][trow + 4];
            ull ap[4] = {a0.u[0], a0.u[1], a1.u[0], a1.u[1]};
            float4 b0 = *(const float4*)&Bs[kk][tcol];
            float4 b1 = *(const float4*)&Bs[kk][tcol + 4];
            ull bp[8] = {dup2(b0.x), dup2(b0.y), dup2(b0.z), dup2(b0.w),
                         dup2(b1.x), dup2(b1.y), dup2(b1.z), dup2(b1.w)};
#pragma unroll
            for (int ip = 0; ip < 4; ip++)
#pragma unroll
                for (int j = 0; j < 8; j++)
                    fma2(acc2[ip][j], ap[ip], bp[j]);
        }
        __syncthreads();
    }

    float accf[8][8];
#pragma unroll
    for (int ip = 0; ip < 4; ip++)
#pragma unroll
        for (int j = 0; j < 8; j++) {
            float2 p = up2(acc2[ip][j]);
            accf[2 * ip][j] = p.x; accf[2 * ip + 1][j] = p.y;
        }

    float4 bv0 = *(const float4*)(bias + bn + tcol);
    float4 bv1 = *(const float4*)(bias + bn + tcol + 4);
    float bb[8] = {bv0.x, bv0.y, bv0.z, bv0.w, bv1.x, bv1.y, bv1.z, bv1.w};
    float rs[8];
#pragma unroll
    for (int i = 0; i < 8; i++) {
        size_t row = (size_t)(bm + trow + i);
        float* cp = C + row * N + bn + tcol;
        float4 v0 = {accf[i][0] + bb[0], accf[i][1] + bb[1], accf[i][2] + bb[2], accf[i][3] + bb[3]};
        float4 v1 = {accf[i][4] + bb[4], accf[i][5] + bb[5], accf[i][6] + bb[6], accf[i][7] + bb[7]};
        *(float4*)cp       = v0;
        *(float4*)(cp + 4) = v1;
        rs[i] = v0.x * v0.x + v0.y * v0.y + v0.z * v0.z + v0.w * v0.w
              + v1.x * v1.x + v1.y * v1.y + v1.z * v1.z + v1.w * v1.w;
    }
    if (cflag == 0) {
        // reduce rs[i] across the 16 lanes sharing trow (xor masks stay in half-warp)
#pragma unroll
        for (int i = 0; i < 8; i++) {
#pragma unroll
            for (int o = 8; o; o >>= 1)
                rs[i] += __shfl_xor_sync(0xffffffffu, rs[i], o);
        }
        if ((tid & 15) == 0) {
#pragma unroll
            for (int i = 0; i < 8; i++)
                atomicAdd(&g_xnorm[bm + trow + i], rs[i]);
        }
    }
}

// ------- GEMM 3: dots = g_X @ E^T, prob epilogue (FFMA2 + __expf) ---------
__global__ __launch_bounds__(256) void gemm_prob_kernel(const float* __restrict__ E)
{
    __shared__ __align__(16) float As[8][128];
    __shared__ __align__(16) float Bs[8][128];
    const int tid  = threadIdx.x;
    const int bm   = blockIdx.y * 128;
    const int bn   = blockIdx.x * 128;
    const int arow = tid >> 1, acol = (tid & 1) * 4;
    const int trow = (tid >> 4) * 8, tcol = (tid & 15) * 8;

    ull acc2[4][8];
#pragma unroll
    for (int ip = 0; ip < 4; ip++)
#pragma unroll
        for (int j = 0; j < 8; j++) acc2[ip][j] = 0ull;

    const float* Ap = g_X + (size_t)(bm + arow) * DIM + acol;
    const float* Ep = E   + (size_t)(bn + arow) * DIM + acol;

    for (int k0 = 0; k0 < DIM; k0 += 8) {
        float4 av = *(const float4*)(Ap + k0);
        As[acol + 0][arow] = av.x; As[acol + 1][arow] = av.y;
        As[acol + 2][arow] = av.z; As[acol + 3][arow] = av.w;
        float4 ev = *(const float4*)(Ep + k0);
        Bs[acol + 0][arow] = ev.x; Bs[acol + 1][arow] = ev.y;
        Bs[acol + 2][arow] = ev.z; Bs[acol + 3][arow] = ev.w;
        __syncthreads();
#pragma unroll
        for (int kk = 0; kk < 8; kk++) {
            U4 a0, a1;
            a0.f = *(const float4*)&As[kk][trow];
            a1.f = *(const float4*)&As[kk][trow + 4];
            ull ap[4] = {a0.u[0], a0.u[1], a1.u[0], a1.u[1]};
            float4 b0 = *(const float4*)&Bs[kk][tcol];
            float4 b1 = *(const float4*)&Bs[kk][tcol + 4];
            ull bp[8] = {dup2(b0.x), dup2(b0.y), dup2(b0.z), dup2(b0.w),
                         dup2(b1.x), dup2(b1.y), dup2(b1.z), dup2(b1.w)};
#pragma unroll
            for (int ip = 0; ip < 4; ip++)
#pragma unroll
                for (int j = 0; j < 8; j++)
                    fma2(acc2[ip][j], ap[ip], bp[j]);
        }
        __syncthreads();
    }

    float accf[8][8];
#pragma unroll
    for (int ip = 0; ip < 4; ip++)
#pragma unroll
        for (int j = 0; j < 8; j++) {
            float2 p = up2(acc2[ip][j]);
            accf[2 * ip][j] = p.x; accf[2 * ip + 1][j] = p.y;
        }

    float4 e0 = *(const float4*)(g_enorm + bn + tcol);
    float4 e1 = *(const float4*)(g_enorm + bn + tcol + 4);
    float er[8] = {e0.x, e0.y, e0.z, e0.w, e1.x, e1.y, e1.z, e1.w};
#pragma unroll
    for (int i = 0; i < 8; i++) {
        size_t row = (size_t)(bm + trow + i);
        float xn = g_xnorm[row];
        float* zp = g_Z + row * KCB + bn + tcol;
        float4 z0 = *(const float4*)zp;
        float4 z1 = *(const float4*)(zp + 4);
        float zr[8] = {z0.x, z0.y, z0.z, z0.w, z1.x, z1.y, z1.z, z1.w};
        float pr[8];
#pragma unroll
        for (int j = 0; j < 8; j++) {
            float dist = xn + er[j] - 2.f * accf[i][j];
            float dd   = dist * (1.f / 400.f);
            float sm   = __expf(-2.f * zr[j]);
            pr[j]      = __expf(zr[j] - 0.5f * dd * sm);
        }
        float4 p0 = {pr[0], pr[1], pr[2], pr[3]};
        float4 p1 = {pr[4], pr[5], pr[6], pr[7]};
        *(float4*)zp       = p0;
        *(float4*)(zp + 4) = p1;
    }
}

// --- normalize: read unnorm g_Z, write Pout + colsum + g_rinv (no g_Z WB) --
__global__ __launch_bounds__(256) void normalize_kernel(float* __restrict__ Pout)
{
    __shared__ float scol[512];
    int tid = threadIdx.x, lane = tid & 31, warp = tid >> 5;
    for (int i = tid; i < 512; i += 256) scol[i] = 0.f;
    __syncthreads();

    int row0 = blockIdx.x * 32 + warp * 4;
    float local[16];
#pragma unroll
    for (int i = 0; i < 16; i++) local[i] = 0.f;

    for (int r = 0; r < 4; r++) {
        size_t base = (size_t)(row0 + r) * KCB;
        float4 v[4];
        float s = 0.f;
#pragma unroll
        for (int c = 0; c < 4; c++) {
            v[c] = *(const float4*)(g_Z + base + c * 128 + lane * 4);
            s += v[c].x + v[c].y + v[c].z + v[c].w;
        }
#pragma unroll
        for (int o = 16; o; o >>= 1) s += __shfl_xor_sync(0xffffffffu, s, o);
        float inv = 1.f / s;
        if (lane == 0) g_rinv[row0 + r] = inv;
#pragma unroll
        for (int c = 0; c < 4; c++) {
            v[c].x *= inv; v[c].y *= inv; v[c].z *= inv; v[c].w *= inv;
            size_t off = base + c * 128 + lane * 4;
            *(float2*)(Pout + off)     = make_float2(v[c].x, v[c].y);
            *(float2*)(Pout + off + 2) = make_float2(v[c].z, v[c].w);
            local[c * 4 + 0] += v[c].x; local[c * 4 + 1] += v[c].y;
            local[c * 4 + 2] += v[c].z; local[c * 4 + 3] += v[c].w;
        }
    }
#pragma unroll
    for (int c = 0; c < 4; c++)
#pragma unroll
        for (int t = 0; t < 4; t++)
            atomicAdd(&scol[c * 128 + lane * 4 + t], local[c * 4 + t]);
    __syncthreads();
    for (int i = tid; i < 512; i += 256) atomicAdd(&g_colsum[i], scol[i]);
}

// ---- GEMM 4: quantized = (g_Z * rinv) @ E ; qst + SSE (FFMA2) ------------
__global__ __launch_bounds__(256) void gemm_quant_kernel(
    const float* __restrict__ E, const float* __restrict__ IN,
    float* __restrict__ Q)
{
    __shared__ __align__(16) float As[8][128];
    __shared__ __align__(16) float Bs[8][128];
    __shared__ double sred[256];
    const int tid  = threadIdx.x;
    const int bm   = blockIdx.y * 128;
    const int bn   = blockIdx.x * 128;
    const int arow = tid >> 1, acol = (tid & 1) * 4;
    const int brow = tid >> 5, bcol = (tid & 31) * 4;
    const int trow = (tid >> 4) * 8, tcol = (tid & 15) * 8;

    ull acc2[4][8];
#pragma unroll
    for (int ip = 0; ip < 4; ip++)
#pragma unroll
        for (int j = 0; j < 8; j++) acc2[ip][j] = 0ull;

    const float rv = g_rinv[bm + arow];
    const float* Ap = g_Z + (size_t)(bm + arow) * KCB + acol;
    const float* Bp = E   + (size_t)brow * DIM + bn + bcol;

    for (int k0 = 0; k0 < KCB; k0 += 8) {
        float4 av = *(const float4*)(Ap + k0);
        As[acol + 0][arow] = av.x * rv; As[acol + 1][arow] = av.y * rv;
        As[acol + 2][arow] = av.z * rv; As[acol + 3][arow] = av.w * rv;
        *(float4*)&Bs[brow][bcol] = *(const float4*)(Bp + (size_t)k0 * DIM);
        __syncthreads();
#pragma unroll
        for (int kk = 0; kk < 8; kk++) {
            U4 a0, a1;
            a0.f = *(const float4*)&As[kk][trow];
            a1.f = *(const float4*)&As[kk][trow + 4];
            ull ap[4] = {a0.u[0], a0.u[1], a1.u[0], a1.u[1]};
            float4 b0 = *(const float4*)&Bs[kk][tcol];
            float4 b1 = *(const float4*)&Bs[kk][tcol + 4];
            ull bp[8] = {dup2(b0.x), dup2(b0.y), dup2(b0.z), dup2(b0.w),
                         dup2(b1.x), dup2(b1.y), dup2(b1.z), dup2(b1.w)};
#pragma unroll
            for (int ip = 0; ip < 4; ip++)
#pragma unroll
                for (int j = 0; j < 8; j++)
                    fma2(acc2[ip][j], ap[ip], bp[j]);
        }
        __syncthreads();
    }

    float accf[8][8];
#pragma unroll
    for (int ip = 0; ip < 4; ip++)
#pragma unroll
        for (int j = 0; j < 8; j++) {
            float2 p = up2(acc2[ip][j]);
            accf[2 * ip][j] = p.x; accf[2 * ip + 1][j] = p.y;
        }

    double lsse = 0.0;
#pragma unroll
    for (int i = 0; i < 8; i++) {
        size_t row = (size_t)(bm + trow + i);
        const float* inp = IN + row * DIM + bn + tcol;
        float* qp = Q + row * DIM + bn + tcol;
        float4 in0 = *(const float4*)inp;
        float4 in1 = *(const float4*)(inp + 4);
        float inr[8] = {in0.x, in0.y, in0.z, in0.w, in1.x, in1.y, in1.z, in1.w};
#pragma unroll
        for (int j = 0; j < 8; j++) {
            float q = accf[i][j];
            float diff = q - inr[j];
            lsse += (double)(diff * diff);
            qp[j] = inr[j] + (q - inr[j]);
        }
    }
    sred[tid] = lsse;
    __syncthreads();
    for (int s = 128; s; s >>= 1) {
        if (tid < s) sred[tid] += sred[tid + s];
        __syncthreads();
    }
    if (tid == 0) atomicAdd(&g_sse, sred[0]);
}

// ---------------- finalize ----------------
__global__ void finalize_kernel(float* __restrict__ loss_ptr,
                                float* __restrict__ ppl_ptr)
{
    __shared__ float sred[512];
    int tid = threadIdx.x;
    float avg = g_colsum[tid] * (1.f / (float)NTOK);
    sred[tid] = avg * logf(avg + 1e-10f);
    __syncthreads();
    for (int s = 256; s; s >>= 1) {
        if (tid < s) sred[tid] += sred[tid + s];
        __syncthreads();
    }
    if (tid == 0) {
        *ppl_ptr  = expf(-sred[0]);
        *loss_ptr = (float)(1.25 * g_sse * (1.0 / ((double)NTOK * (double)DIM)));
    }
}

extern "C" void kernel_launch(void* const* d_in, const int* in_sizes, int n_in,
                              void* d_out, int out_size)
{
    (void)in_sizes; (void)n_in; (void)out_size;
    const float* x   = (const float*)d_in[0];
    const float* mW  = (const float*)d_in[1];
    const float* mb  = (const float*)d_in[2];
    const float* lW  = (const float*)d_in[3];
    const float* lb  = (const float*)d_in[4];
    const float* emb = (const float*)d_in[5];

    float* o         = (float*)d_out;
    float* loss_ptr  = o;
    float* q_ptr     = o + 1;
    float* ppl_ptr   = o + 1 + NDsz;
    float* probs_ptr = o + 2 + NDsz;

    dim3 g4(KCB / 128, NTOK / 128);

    init_kernel<<<256, 256>>>();
    rownorm2_kernel<<<KCB / 8, 256>>>(emb);                            // enorm
    sgemm_bias_kernel<<<g4, 256>>>(x, mW, mb, 0, 0, NTOK, DIM, DIM);   // x + fused xnorm
    sgemm_bias_kernel<<<g4, 256>>>(nullptr, lW, lb, 1, 1, NTOK, KCB, DIM); // z
    gemm_prob_kernel<<<g4, 256>>>(emb);                                // unnorm prob
    normalize_kernel<<<NTOK / 32, 256>>>(probs_ptr);                   // Pout + colsum + rinv
    gemm_quant_kernel<<<dim3(DIM / 128, NTOK / 128), 256>>>(emb, x, q_ptr);
    finalize_kernel<<<1, 512>>>(loss_ptr, ppl_ptr);
}

// round 14
// speedup vs baseline: 1.2004x; 1.0884x over previous
#include <cuda_runtime.h>
#include <stdint.h>
#include <math.h>

#define NTOK 65536
#define DIM  512
#define KCB  512
#define NDsz ((size_t)NTOK * (size_t)DIM)
typedef unsigned long long ull;

// chunk-padded column mapping for B smem: 16 chunks of 8 floats, stride 12
#define SCOL(j) ((((j) >> 3) * 12) + ((j) & 7))

// ---- scratch ----
__device__ float  g_X[NDsz];
__device__ float  g_Z[NDsz];      // z -> unnormalized probs
__device__ float  g_xnorm[NTOK];
__device__ float  g_rinv[NTOK];
__device__ float  g_enorm[KCB];
__device__ float  g_colsum[KCB];
__device__ double g_sse;

// ---- packed fp32x2 helpers ----
__device__ __forceinline__ void fma2(ull& c, ull a, ull b) {
    asm("fma.rn.f32x2 %0, %1, %2, %0;" : "+l"(c) : "l"(a), "l"(b));
}
__device__ __forceinline__ ull dup2(float v) {
    ull r;
    asm("mov.b64 %0, {%1, %1};" : "=l"(r) : "f"(v));
    return r;
}
__device__ __forceinline__ float2 up2(ull v) {
    float2 f;
    asm("mov.b64 {%0, %1}, %2;" : "=f"(f.x), "=f"(f.y) : "l"(v));
    return f;
}
union U4 { float4 f; ull u[2]; };

// ---------------- init ----------------
__global__ void init_kernel() {
    int i = blockIdx.x * blockDim.x + threadIdx.x;
    if (i < NTOK) g_xnorm[i] = 0.f;
    if (i < KCB)  g_colsum[i] = 0.f;
    if (i == 0)   g_sse = 0.0;
}

// ---- embedding row norms ----
__global__ void rownorm2_kernel(const float* __restrict__ Aext) {
    int lane = threadIdx.x & 31;
    int warp = threadIdx.x >> 5;
    int row  = blockIdx.x * 8 + warp;
    if (row >= KCB) return;
    const float* p = Aext + (size_t)row * 512;
    float s = 0.f;
#pragma unroll
    for (int c = 0; c < 4; c++) {
        float4 v = *(const float4*)(p + c * 128 + lane * 4);
        s += v.x * v.x + v.y * v.y + v.z * v.z + v.w * v.w;
    }
#pragma unroll
    for (int o = 16; o; o >>= 1) s += __shfl_xor_sync(0xffffffffu, s, o);
    if (lane == 0) g_enorm[row] = s;
}

// ---------------- GEMM 1&2: C = A @ B + bias (FFMA2, swizzled B) ----------
__global__ __launch_bounds__(256) void sgemm_bias_kernel(
    const float* __restrict__ Aext, const float* __restrict__ B,
    const float* __restrict__ bias, int aflag, int cflag,
    int M, int N, int K)
{
    __shared__ __align__(16) float As[8][128];
    __shared__ __align__(16) float Bs[8][192];
    const int tid  = threadIdx.x;
    const int bm   = blockIdx.y * 128;
    const int bn   = blockIdx.x * 128;
    const int arow = tid >> 1, acol = (tid & 1) * 4;
    const int brow = tid >> 5, bcol = (tid & 31) * 4;
    const int trow = (tid >> 4) * 8, tcq = (tid & 15) * 12, tcol = (tid & 15) * 8;

    const float* A = aflag ? g_X : Aext;
    float*       C = cflag ? g_Z : g_X;

    ull acc2[4][8];
#pragma unroll
    for (int ip = 0; ip < 4; ip++)
#pragma unroll
        for (int j = 0; j < 8; j++) acc2[ip][j] = 0ull;

    const float* Ap = A + (size_t)(bm + arow) * K + acol;
    const float* Bp = B + (size_t)brow * N + bn + bcol;
    const int bsc = SCOL(bcol);

    for (int k0 = 0; k0 < K; k0 += 8) {
        float4 av = *(const float4*)(Ap + k0);
        As[acol + 0][arow] = av.x; As[acol + 1][arow] = av.y;
        As[acol + 2][arow] = av.z; As[acol + 3][arow] = av.w;
        *(float4*)&Bs[brow][bsc] = *(const float4*)(Bp + (size_t)k0 * N);
        __syncthreads();
#pragma unroll
        for (int kk = 0; kk < 8; kk++) {
            U4 a0, a1;
            a0.f = *(const float4*)&As[kk][trow];
            a1.f = *(const float4*)&As[kk][trow + 4];
            ull ap[4] = {a0.u[0], a0.u[1], a1.u[0], a1.u[1]};
            float4 b0 = *(const float4*)&Bs[kk][tcq];
            float4 b1 = *(const float4*)&Bs[kk][tcq + 4];
            ull bp[8] = {dup2(b0.x), dup2(b0.y), dup2(b0.z), dup2(b0.w),
                         dup2(b1.x), dup2(b1.y), dup2(b1.z), dup2(b1.w)};
#pragma unroll
            for (int ip = 0; ip < 4; ip++)
#pragma unroll
                for (int j = 0; j < 8; j++)
                    fma2(acc2[ip][j], ap[ip], bp[j]);
        }
        __syncthreads();
    }

    float accf[8][8];
#pragma unroll
    for (int ip = 0; ip < 4; ip++)
#pragma unroll
        for (int j = 0; j < 8; j++) {
            float2 p = up2(acc2[ip][j]);
            accf[2 * ip][j] = p.x; accf[2 * ip + 1][j] = p.y;
        }

    float4 bv0 = *(const float4*)(bias + bn + tcol);
    float4 bv1 = *(const float4*)(bias + bn + tcol + 4);
    float bb[8] = {bv0.x, bv0.y, bv0.z, bv0.w, bv1.x, bv1.y, bv1.z, bv1.w};
    float rs[8];
#pragma unroll
    for (int i = 0; i < 8; i++) {
        size_t row = (size_t)(bm + trow + i);
        float* cp = C + row * N + bn + tcol;
        float4 v0 = {accf[i][0] + bb[0], accf[i][1] + bb[1], accf[i][2] + bb[2], accf[i][3] + bb[3]};
        float4 v1 = {accf[i][4] + bb[4], accf[i][5] + bb[5], accf[i][6] + bb[6], accf[i][7] + bb[7]};
        *(float4*)cp       = v0;
        *(float4*)(cp + 4) = v1;
        rs[i] = v0.x * v0.x + v0.y * v0.y + v0.z * v0.z + v0.w * v0.w
              + v1.x * v1.x + v1.y * v1.y + v1.z * v1.z + v1.w * v1.w;
    }
    if (cflag == 0) {
#pragma unroll
        for (int i = 0; i < 8; i++) {
#pragma unroll
            for (int o = 8; o; o >>= 1)
                rs[i] += __shfl_xor_sync(0xffffffffu, rs[i], o);
        }
        if ((tid & 15) == 0) {
#pragma unroll
            for (int i = 0; i < 8; i++)
                atomicAdd(&g_xnorm[bm + trow + i], rs[i]);
        }
    }
}

// ------- GEMM 3: dots = g_X @ E^T, prob epilogue (FFMA2 + __expf) ---------
__global__ __launch_bounds__(256) void gemm_prob_kernel(const float* __restrict__ E)
{
    __shared__ __align__(16) float As[8][128];
    __shared__ __align__(16) float Bs[8][192];
    const int tid  = threadIdx.x;
    const int bm   = blockIdx.y * 128;
    const int bn   = blockIdx.x * 128;
    const int arow = tid >> 1, acol = (tid & 1) * 4;
    const int trow = (tid >> 4) * 8, tcq = (tid & 15) * 12, tcol = (tid & 15) * 8;
    const int asc = SCOL(arow);

    ull acc2[4][8];
#pragma unroll
    for (int ip = 0; ip < 4; ip++)
#pragma unroll
        for (int j = 0; j < 8; j++) acc2[ip][j] = 0ull;

    const float* Ap = g_X + (size_t)(bm + arow) * DIM + acol;
    const float* Ep = E   + (size_t)(bn + arow) * DIM + acol;

    for (int k0 = 0; k0 < DIM; k0 += 8) {
        float4 av = *(const float4*)(Ap + k0);
        As[acol + 0][arow] = av.x; As[acol + 1][arow] = av.y;
        As[acol + 2][arow] = av.z; As[acol + 3][arow] = av.w;
        float4 ev = *(const float4*)(Ep + k0);
        Bs[acol + 0][asc] = ev.x; Bs[acol + 1][asc] = ev.y;
        Bs[acol + 2][asc] = ev.z; Bs[acol + 3][asc] = ev.w;
        __syncthreads();
#pragma unroll
        for (int kk = 0; kk < 8; kk++) {
            U4 a0, a1;
            a0.f = *(const float4*)&As[kk][trow];
            a1.f = *(const float4*)&As[kk][trow + 4];
            ull ap[4] = {a0.u[0], a0.u[1], a1.u[0], a1.u[1]};
            float4 b0 = *(const float4*)&Bs[kk][tcq];
            float4 b1 = *(const float4*)&Bs[kk][tcq + 4];
            ull bp[8] = {dup2(b0.x), dup2(b0.y), dup2(b0.z), dup2(b0.w),
                         dup2(b1.x), dup2(b1.y), dup2(b1.z), dup2(b1.w)};
#pragma unroll
            for (int ip = 0; ip < 4; ip++)
#pragma unroll
                for (int j = 0; j < 8; j++)
                    fma2(acc2[ip][j], ap[ip], bp[j]);
        }
        __syncthreads();
    }

    float accf[8][8];
#pragma unroll
    for (int ip = 0; ip < 4; ip++)
#pragma unroll
        for (int j = 0; j < 8; j++) {
            float2 p = up2(acc2[ip][j]);
            accf[2 * ip][j] = p.x; accf[2 * ip + 1][j] = p.y;
        }

    float4 e0 = *(const float4*)(g_enorm + bn + tcol);
    float4 e1 = *(const float4*)(g_enorm + bn + tcol + 4);
    float er[8] = {e0.x, e0.y, e0.z, e0.w, e1.x, e1.y, e1.z, e1.w};
#pragma unroll
    for (int i = 0; i < 8; i++) {
        size_t row = (size_t)(bm + trow + i);
        float xn = g_xnorm[row];
        float* zp = g_Z + row * KCB + bn + tcol;
        float4 z0 = *(const float4*)zp;
        float4 z1 = *(const float4*)(zp + 4);
        float zr[8] = {z0.x, z0.y, z0.z, z0.w, z1.x, z1.y, z1.z, z1.w};
        float pr[8];
#pragma unroll
        for (int j = 0; j < 8; j++) {
            float dist = xn + er[j] - 2.f * accf[i][j];
            float dd   = dist * (1.f / 400.f);
            float sm   = __expf(-2.f * zr[j]);
            pr[j]      = __expf(zr[j] - 0.5f * dd * sm);
        }
        float4 p0 = {pr[0], pr[1], pr[2], pr[3]};
        float4 p1 = {pr[4], pr[5], pr[6], pr[7]};
        *(float4*)zp       = p0;
        *(float4*)(zp + 4) = p1;
    }
}

// --- normalize: Pout + colsum + g_rinv (no g_Z writeback) ---
__global__ __launch_bounds__(256) void normalize_kernel(float* __restrict__ Pout)
{
    __shared__ float scol[512];
    int tid = threadIdx.x, lane = tid & 31, warp = tid >> 5;
    for (int i = tid; i < 512; i += 256) scol[i] = 0.f;
    __syncthreads();

    int row0 = blockIdx.x * 32 + warp * 4;
    float local[16];
#pragma unroll
    for (int i = 0; i < 16; i++) local[i] = 0.f;

    for (int r = 0; r < 4; r++) {
        size_t base = (size_t)(row0 + r) * KCB;
        float4 v[4];
        float s = 0.f;
#pragma unroll
        for (int c = 0; c < 4; c++) {
            v[c] = *(const float4*)(g_Z + base + c * 128 + lane * 4);
            s += v[c].x + v[c].y + v[c].z + v[c].w;
        }
#pragma unroll
        for (int o = 16; o; o >>= 1) s += __shfl_xor_sync(0xffffffffu, s, o);
        float inv = 1.f / s;
        if (lane == 0) g_rinv[row0 + r] = inv;
#pragma unroll
        for (int c = 0; c < 4; c++) {
            v[c].x *= inv; v[c].y *= inv; v[c].z *= inv; v[c].w *= inv;
            size_t off = base + c * 128 + lane * 4;
            *(float2*)(Pout + off)     = make_float2(v[c].x, v[c].y);
            *(float2*)(Pout + off + 2) = make_float2(v[c].z, v[c].w);
            local[c * 4 + 0] += v[c].x; local[c * 4 + 1] += v[c].y;
            local[c * 4 + 2] += v[c].z; local[c * 4 + 3] += v[c].w;
        }
    }
#pragma unroll
    for (int c = 0; c < 4; c++)
#pragma unroll
        for (int t = 0; t < 4; t++)
            atomicAdd(&scol[c * 128 + lane * 4 + t], local[c * 4 + t]);
    __syncthreads();
    for (int i = tid; i < 512; i += 256) atomicAdd(&g_colsum[i], scol[i]);
}

// ---- GEMM 4: quantized = (g_Z * rinv) @ E ; qst + SSE (FFMA2, swizzled) --
__global__ __launch_bounds__(256) void gemm_quant_kernel(
    const float* __restrict__ E, const float* __restrict__ IN,
    float* __restrict__ Q)
{
    __shared__ __align__(16) float As[8][128];
    __shared__ __align__(16) float Bs[8][192];
    __shared__ double sred[256];
    const int tid  = threadIdx.x;
    const int bm   = blockIdx.y * 128;
    const int bn   = blockIdx.x * 128;
    const int arow = tid >> 1, acol = (tid & 1) * 4;
    const int brow = tid >> 5, bcol = (tid & 31) * 4;
    const int trow = (tid >> 4) * 8, tcq = (tid & 15) * 12, tcol = (tid & 15) * 8;

    ull acc2[4][8];
#pragma unroll
    for (int ip = 0; ip < 4; ip++)
#pragma unroll
        for (int j = 0; j < 8; j++) acc2[ip][j] = 0ull;

    const float rv = g_rinv[bm + arow];
    const float* Ap = g_Z + (size_t)(bm + arow) * KCB + acol;
    const float* Bp = E   + (size_t)brow * DIM + bn + bcol;
    const int bsc = SCOL(bcol);

    for (int k0 = 0; k0 < KCB; k0 += 8) {
        float4 av = *(const float4*)(Ap + k0);
        As[acol + 0][arow] = av.x * rv; As[acol + 1][arow] = av.y * rv;
        As[acol + 2][arow] = av.z * rv; As[acol + 3][arow] = av.w * rv;
        *(float4*)&Bs[brow][bsc] = *(const float4*)(Bp + (size_t)k0 * DIM);
        __syncthreads();
#pragma unroll
        for (int kk = 0; kk < 8; kk++) {
            U4 a0, a1;
            a0.f = *(const float4*)&As[kk][trow];
            a1.f = *(const float4*)&As[kk][trow + 4];
            ull ap[4] = {a0.u[0], a0.u[1], a1.u[0], a1.u[1]};
            float4 b0 = *(const float4*)&Bs[kk][tcq];
            float4 b1 = *(const float4*)&Bs[kk][tcq + 4];
            ull bp[8] = {dup2(b0.x), dup2(b0.y), dup2(b0.z), dup2(b0.w),
                         dup2(b1.x), dup2(b1.y), dup2(b1.z), dup2(b1.w)};
#pragma unroll
            for (int ip = 0; ip < 4; ip++)
#pragma unroll
                for (int j = 0; j < 8; j++)
                    fma2(acc2[ip][j], ap[ip], bp[j]);
        }
        __syncthreads();
    }

    float accf[8][8];
#pragma unroll
    for (int ip = 0; ip < 4; ip++)
#pragma unroll
        for (int j = 0; j < 8; j++) {
            float2 p = up2(acc2[ip][j]);
            accf[2 * ip][j] = p.x; accf[2 * ip + 1][j] = p.y;
        }

    double lsse = 0.0;
#pragma unroll
    for (int i = 0; i < 8; i++) {
        size_t row = (size_t)(bm + trow + i);
        const float* inp = IN + row * DIM + bn + tcol;
        float* qp = Q + row * DIM + bn + tcol;
        float4 in0 = *(const float4*)inp;
        float4 in1 = *(const float4*)(inp + 4);
        float inr[8] = {in0.x, in0.y, in0.z, in0.w, in1.x, in1.y, in1.z, in1.w};
#pragma unroll
        for (int j = 0; j < 8; j++) {
            float q = accf[i][j];
            float diff = q - inr[j];
            lsse += (double)(diff * diff);
            qp[j] = inr[j] + (q - inr[j]);
        }
    }
    sred[tid] = lsse;
    __syncthreads();
    for (int s = 128; s; s >>= 1) {
        if (tid < s) sred[tid] += sred[tid + s];
        __syncthreads();
    }
    if (tid == 0) atomicAdd(&g_sse, sred[0]);
}

// ---------------- finalize ----------------
__global__ void finalize_kernel(float* __restrict__ loss_ptr,
                                float* __restrict__ ppl_ptr)
{
    __shared__ float sred[512];
    int tid = threadIdx.x;
    float avg = g_colsum[tid] * (1.f / (float)NTOK);
    sred[tid] = avg * logf(avg + 1e-10f);
    __syncthreads();
    for (int s = 256; s; s >>= 1) {
        if (tid < s) sred[tid] += sred[tid + s];
        __syncthreads();
    }
    if (tid == 0) {
        *ppl_ptr  = expf(-sred[0]);
        *loss_ptr = (float)(1.25 * g_sse * (1.0 / ((double)NTOK * (double)DIM)));
    }
}

extern "C" void kernel_launch(void* const* d_in, const int* in_sizes, int n_in,
                              void* d_out, int out_size)
{
    (void)in_sizes; (void)n_in; (void)out_size;
    const float* x   = (const float*)d_in[0];
    const float* mW  = (const float*)d_in[1];
    const float* mb  = (const float*)d_in[2];
    const float* lW  = (const float*)d_in[3];
    const float* lb  = (const float*)d_in[4];
    const float* emb = (const float*)d_in[5];

    float* o         = (float*)d_out;
    float* loss_ptr  = o;
    float* q_ptr     = o + 1;
    float* ppl_ptr   = o + 1 + NDsz;
    float* probs_ptr = o + 2 + NDsz;

    dim3 g4(KCB / 128, NTOK / 128);

    init_kernel<<<256, 256>>>();
    rownorm2_kernel<<<KCB / 8, 256>>>(emb);                            // enorm
    sgemm_bias_kernel<<<g4, 256>>>(x, mW, mb, 0, 0, NTOK, DIM, DIM);   // x + fused xnorm
    sgemm_bias_kernel<<<g4, 256>>>(nullptr, lW, lb, 1, 1, NTOK, KCB, DIM); // z
    gemm_prob_kernel<<<g4, 256>>>(emb);                                // unnorm prob
    normalize_kernel<<<NTOK / 32, 256>>>(probs_ptr);                   // Pout + colsum + rinv
    gemm_quant_kernel<<<dim3(DIM / 128, NTOK / 128), 256>>>(emb, x, q_ptr);
    finalize_kernel<<<1, 512>>>(loss_ptr, ppl_ptr);
}

// round 15
// speedup vs baseline: 1.5944x; 1.3283x over previous
#include <cuda_runtime.h>
#include <stdint.h>
#include <math.h>

#define NTOK 65536
#define DIM  512
#define KCB  512
#define NDsz ((size_t)NTOK * (size_t)DIM)
typedef unsigned long long ull;

// chunk-padded column mapping for B smem: 16 chunks of 8 floats, stride 12
#define SCOL(j) ((((j) >> 3) * 12) + ((j) & 7))

// ---- scratch ----
__device__ float  g_X[NDsz];
__device__ float  g_Z[NDsz];      // z -> unnormalized probs
__device__ float  g_xnorm[NTOK];
__device__ float  g_rinv[NTOK];
__device__ float  g_enorm[KCB];
__device__ float  g_colsum[KCB];
__device__ double g_sse;

// ---- packed fp32x2 helpers ----
__device__ __forceinline__ void fma2(ull& c, ull a, ull b) {
    asm("fma.rn.f32x2 %0, %1, %2, %0;" : "+l"(c) : "l"(a), "l"(b));
}
__device__ __forceinline__ ull dup2(float v) {
    ull r;
    asm("mov.b64 %0, {%1, %1};" : "=l"(r) : "f"(v));
    return r;
}
__device__ __forceinline__ float2 up2(ull v) {
    float2 f;
    asm("mov.b64 {%0, %1}, %2;" : "=f"(f.x), "=f"(f.y) : "l"(v));
    return f;
}
union U4 { float4 f; ull u[2]; };

// ---------------- init ----------------
__global__ void init_kernel() {
    int i = blockIdx.x * blockDim.x + threadIdx.x;
    if (i < NTOK) g_xnorm[i] = 0.f;
    if (i < KCB)  g_colsum[i] = 0.f;
    if (i == 0)   g_sse = 0.0;
}

// ---- embedding row norms ----
__global__ void rownorm2_kernel(const float* __restrict__ Aext) {
    int lane = threadIdx.x & 31;
    int warp = threadIdx.x >> 5;
    int row  = blockIdx.x * 8 + warp;
    if (row >= KCB) return;
    const float* p = Aext + (size_t)row * 512;
    float s = 0.f;
#pragma unroll
    for (int c = 0; c < 4; c++) {
        float4 v = *(const float4*)(p + c * 128 + lane * 4);
        s += v.x * v.x + v.y * v.y + v.z * v.z + v.w * v.w;
    }
#pragma unroll
    for (int o = 16; o; o >>= 1) s += __shfl_xor_sync(0xffffffffu, s, o);
    if (lane == 0) g_enorm[row] = s;
}

// shared compute body: one 8-deep K-chunk of FFMA2 on (As, Bs)
#define CHUNK_FFMA2(AsB, BsB)                                               \
    _Pragma("unroll")                                                       \
    for (int kk = 0; kk < 8; kk++) {                                        \
        U4 a0, a1;                                                          \
        a0.f = *(const float4*)&(AsB)[kk][trow];                            \
        a1.f = *(const float4*)&(AsB)[kk][trow + 4];                        \
        ull ap[4] = {a0.u[0], a0.u[1], a1.u[0], a1.u[1]};                   \
        float4 b0 = *(const float4*)&(BsB)[kk][tcq];                        \
        float4 b1 = *(const float4*)&(BsB)[kk][tcq + 4];                    \
        ull bp[8] = {dup2(b0.x), dup2(b0.y), dup2(b0.z), dup2(b0.w),        \
                     dup2(b1.x), dup2(b1.y), dup2(b1.z), dup2(b1.w)};       \
        _Pragma("unroll")                                                   \
        for (int ip = 0; ip < 4; ip++)                                      \
            _Pragma("unroll")                                               \
            for (int j = 0; j < 8; j++)                                     \
                fma2(acc2[ip][j], ap[ip], bp[j]);                           \
    }

// ---------------- GEMM 1&2: C = A @ B + bias (FFMA2, pipelined) -----------
__global__ __launch_bounds__(256, 2) void sgemm_bias_kernel(
    const float* __restrict__ Aext, const float* __restrict__ B,
    const float* __restrict__ bias, int aflag, int cflag,
    int M, int N, int K)
{
    __shared__ __align__(16) float As[2][8][128];
    __shared__ __align__(16) float Bs[2][8][192];
    const int tid  = threadIdx.x;
    const int bm   = blockIdx.y * 128;
    const int bn   = blockIdx.x * 128;
    const int arow = tid >> 1, acol = (tid & 1) * 4;
    const int brow = tid >> 5, bcol = (tid & 31) * 4;
    const int trow = (tid >> 4) * 8, tcq = (tid & 15) * 12, tcol = (tid & 15) * 8;

    const float* A = aflag ? g_X : Aext;
    float*       C = cflag ? g_Z : g_X;

    ull acc2[4][8];
#pragma unroll
    for (int ip = 0; ip < 4; ip++)
#pragma unroll
        for (int j = 0; j < 8; j++) acc2[ip][j] = 0ull;

    const float* Ap = A + (size_t)(bm + arow) * K + acol;
    const float* Bp = B + (size_t)brow * N + bn + bcol;
    const int bsc = SCOL(bcol);

    float4 av = *(const float4*)Ap;
    float4 bv = *(const float4*)Bp;
    As[0][acol + 0][arow] = av.x; As[0][acol + 1][arow] = av.y;
    As[0][acol + 2][arow] = av.z; As[0][acol + 3][arow] = av.w;
    *(float4*)&Bs[0][brow][bsc] = bv;
    __syncthreads();

    const int NCH = K / 8;
    for (int c = 0; c < NCH; c++) {
        const int cur = c & 1;
        if (c + 1 < NCH) {
            av = *(const float4*)(Ap + (c + 1) * 8);
            bv = *(const float4*)(Bp + (size_t)(c + 1) * 8 * N);
        }
        CHUNK_FFMA2(As[cur], Bs[cur]);
        if (c + 1 < NCH) {
            const int nxt = cur ^ 1;
            As[nxt][acol + 0][arow] = av.x; As[nxt][acol + 1][arow] = av.y;
            As[nxt][acol + 2][arow] = av.z; As[nxt][acol + 3][arow] = av.w;
            *(float4*)&Bs[nxt][brow][bsc] = bv;
        }
        __syncthreads();
    }

    float accf[8][8];
#pragma unroll
    for (int ip = 0; ip < 4; ip++)
#pragma unroll
        for (int j = 0; j < 8; j++) {
            float2 p = up2(acc2[ip][j]);
            accf[2 * ip][j] = p.x; accf[2 * ip + 1][j] = p.y;
        }

    float4 bv0 = *(const float4*)(bias + bn + tcol);
    float4 bv1 = *(const float4*)(bias + bn + tcol + 4);
    float bb[8] = {bv0.x, bv0.y, bv0.z, bv0.w, bv1.x, bv1.y, bv1.z, bv1.w};
    float rs[8];
#pragma unroll
    for (int i = 0; i < 8; i++) {
        size_t row = (size_t)(bm + trow + i);
        float* cp = C + row * N + bn + tcol;
        float4 v0 = {accf[i][0] + bb[0], accf[i][1] + bb[1], accf[i][2] + bb[2], accf[i][3] + bb[3]};
        float4 v1 = {accf[i][4] + bb[4], accf[i][5] + bb[5], accf[i][6] + bb[6], accf[i][7] + bb[7]};
        *(float4*)cp       = v0;
        *(float4*)(cp + 4) = v1;
        rs[i] = v0.x * v0.x + v0.y * v0.y + v0.z * v0.z + v0.w * v0.w
              + v1.x * v1.x + v1.y * v1.y + v1.z * v1.z + v1.w * v1.w;
    }
    if (cflag == 0) {
#pragma unroll
        for (int i = 0; i < 8; i++) {
#pragma unroll
            for (int o = 8; o; o >>= 1)
                rs[i] += __shfl_xor_sync(0xffffffffu, rs[i], o);
        }
        if ((tid & 15) == 0) {
#pragma unroll
            for (int i = 0; i < 8; i++)
                atomicAdd(&g_xnorm[bm + trow + i], rs[i]);
        }
    }
}

// ------- GEMM 3: dots = g_X @ E^T, prob epilogue (FFMA2, pipelined) -------
__global__ __launch_bounds__(256, 2) void gemm_prob_kernel(const float* __restrict__ E)
{
    __shared__ __align__(16) float As[2][8][128];
    __shared__ __align__(16) float Bs[2][8][192];
    const int tid  = threadIdx.x;
    const int bm   = blockIdx.y * 128;
    const int bn   = blockIdx.x * 128;
    const int arow = tid >> 1, acol = (tid & 1) * 4;
    const int trow = (tid >> 4) * 8, tcq = (tid & 15) * 12, tcol = (tid & 15) * 8;
    const int asc = SCOL(arow);

    ull acc2[4][8];
#pragma unroll
    for (int ip = 0; ip < 4; ip++)
#pragma unroll
        for (int j = 0; j < 8; j++) acc2[ip][j] = 0ull;

    const float* Ap = g_X + (size_t)(bm + arow) * DIM + acol;
    const float* Ep = E   + (size_t)(bn + arow) * DIM + acol;

    float4 av = *(const float4*)Ap;
    float4 ev = *(const float4*)Ep;
    As[0][acol + 0][arow] = av.x; As[0][acol + 1][arow] = av.y;
    As[0][acol + 2][arow] = av.z; As[0][acol + 3][arow] = av.w;
    Bs[0][acol + 0][asc] = ev.x; Bs[0][acol + 1][asc] = ev.y;
    Bs[0][acol + 2][asc] = ev.z; Bs[0][acol + 3][asc] = ev.w;
    __syncthreads();

    for (int c = 0; c < 64; c++) {
        const int cur = c & 1;
        if (c < 63) {
            av = *(const float4*)(Ap + (c + 1) * 8);
            ev = *(const float4*)(Ep + (c + 1) * 8);
        }
        CHUNK_FFMA2(As[cur], Bs[cur]);
        if (c < 63) {
            const int nxt = cur ^ 1;
            As[nxt][acol + 0][arow] = av.x; As[nxt][acol + 1][arow] = av.y;
            As[nxt][acol + 2][arow] = av.z; As[nxt][acol + 3][arow] = av.w;
            Bs[nxt][acol + 0][asc] = ev.x; Bs[nxt][acol + 1][asc] = ev.y;
            Bs[nxt][acol + 2][asc] = ev.z; Bs[nxt][acol + 3][asc] = ev.w;
        }
        __syncthreads();
    }

    float accf[8][8];
#pragma unroll
    for (int ip = 0; ip < 4; ip++)
#pragma unroll
        for (int j = 0; j < 8; j++) {
            float2 p = up2(acc2[ip][j]);
            accf[2 * ip][j] = p.x; accf[2 * ip + 1][j] = p.y;
        }

    float4 e0 = *(const float4*)(g_enorm + bn + tcol);
    float4 e1 = *(const float4*)(g_enorm + bn + tcol + 4);
    float er[8] = {e0.x, e0.y, e0.z, e0.w, e1.x, e1.y, e1.z, e1.w};
#pragma unroll
    for (int i = 0; i < 8; i++) {
        size_t row = (size_t)(bm + trow + i);
        float xn = g_xnorm[row];
        float* zp = g_Z + row * KCB + bn + tcol;
        float4 z0 = *(const float4*)zp;
        float4 z1 = *(const float4*)(zp + 4);
        float zr[8] = {z0.x, z0.y, z0.z, z0.w, z1.x, z1.y, z1.z, z1.w};
        float pr[8];
#pragma unroll
        for (int j = 0; j < 8; j++) {
            float dist = xn + er[j] - 2.f * accf[i][j];
            float dd   = dist * (1.f / 400.f);
            float sm   = __expf(-2.f * zr[j]);
            pr[j]      = __expf(zr[j] - 0.5f * dd * sm);
        }
        float4 p0 = {pr[0], pr[1], pr[2], pr[3]};
        float4 p1 = {pr[4], pr[5], pr[6], pr[7]};
        *(float4*)zp       = p0;
        *(float4*)(zp + 4) = p1;
    }
}

// --- normalize: Pout + colsum + g_rinv (no g_Z writeback) ---
__global__ __launch_bounds__(256) void normalize_kernel(float* __restrict__ Pout)
{
    __shared__ float scol[512];
    int tid = threadIdx.x, lane = tid & 31, warp = tid >> 5;
    for (int i = tid; i < 512; i += 256) scol[i] = 0.f;
    __syncthreads();

    int row0 = blockIdx.x * 32 + warp * 4;
    float local[16];
#pragma unroll
    for (int i = 0; i < 16; i++) local[i] = 0.f;

    for (int r = 0; r < 4; r++) {
        size_t base = (size_t)(row0 + r) * KCB;
        float4 v[4];
        float s = 0.f;
#pragma unroll
        for (int c = 0; c < 4; c++) {
            v[c] = *(const float4*)(g_Z + base + c * 128 + lane * 4);
            s += v[c].x + v[c].y + v[c].z + v[c].w;
        }
#pragma unroll
        for (int o = 16; o; o >>= 1) s += __shfl_xor_sync(0xffffffffu, s, o);
        float inv = 1.f / s;
        if (lane == 0) g_rinv[row0 + r] = inv;
#pragma unroll
        for (int c = 0; c < 4; c++) {
            v[c].x *= inv; v[c].y *= inv; v[c].z *= inv; v[c].w *= inv;
            size_t off = base + c * 128 + lane * 4;
            *(float2*)(Pout + off)     = make_float2(v[c].x, v[c].y);
            *(float2*)(Pout + off + 2) = make_float2(v[c].z, v[c].w);
            local[c * 4 + 0] += v[c].x; local[c * 4 + 1] += v[c].y;
            local[c * 4 + 2] += v[c].z; local[c * 4 + 3] += v[c].w;
        }
    }
#pragma unroll
    for (int c = 0; c < 4; c++)
#pragma unroll
        for (int t = 0; t < 4; t++)
            atomicAdd(&scol[c * 128 + lane * 4 + t], local[c * 4 + t]);
    __syncthreads();
    for (int i = tid; i < 512; i += 256) atomicAdd(&g_colsum[i], scol[i]);
}

// ---- GEMM 4: quantized = (g_Z * rinv) @ E ; qst + SSE (FFMA2, pipelined) -
__global__ __launch_bounds__(256, 2) void gemm_quant_kernel(
    const float* __restrict__ E, const float* __restrict__ IN,
    float* __restrict__ Q)
{
    __shared__ __align__(16) float As[2][8][128];
    __shared__ __align__(16) float Bs[2][8][192];
    __shared__ double sred[256];
    const int tid  = threadIdx.x;
    const int bm   = blockIdx.y * 128;
    const int bn   = blockIdx.x * 128;
    const int arow = tid >> 1, acol = (tid & 1) * 4;
    const int brow = tid >> 5, bcol = (tid & 31) * 4;
    const int trow = (tid >> 4) * 8, tcq = (tid & 15) * 12, tcol = (tid & 15) * 8;

    ull acc2[4][8];
#pragma unroll
    for (int ip = 0; ip < 4; ip++)
#pragma unroll
        for (int j = 0; j < 8; j++) acc2[ip][j] = 0ull;

    const float rv = g_rinv[bm + arow];
    const float* Ap = g_Z + (size_t)(bm + arow) * KCB + acol;
    const float* Bp = E   + (size_t)brow * DIM + bn + bcol;
    const int bsc = SCOL(bcol);

    float4 av = *(const float4*)Ap;
    float4 bv = *(const float4*)Bp;
    As[0][acol + 0][arow] = av.x * rv; As[0][acol + 1][arow] = av.y * rv;
    As[0][acol + 2][arow] = av.z * rv; As[0][acol + 3][arow] = av.w * rv;
    *(float4*)&Bs[0][brow][bsc] = bv;
    __syncthreads();

    for (int c = 0; c < 64; c++) {
        const int cur = c & 1;
        if (c < 63) {
            av = *(const float4*)(Ap + (c + 1) * 8);
            bv = *(const float4*)(Bp + (size_t)(c + 1) * 8 * DIM);
        }
        CHUNK_FFMA2(As[cur], Bs[cur]);
        if (c < 63) {
            const int nxt = cur ^ 1;
            As[nxt][acol + 0][arow] = av.x * rv; As[nxt][acol + 1][arow] = av.y * rv;
            As[nxt][acol + 2][arow] = av.z * rv; As[nxt][acol + 3][arow] = av.w * rv;
            *(float4*)&Bs[nxt][brow][bsc] = bv;
        }
        __syncthreads();
    }

    float accf[8][8];
#pragma unroll
    for (int ip = 0; ip < 4; ip++)
#pragma unroll
        for (int j = 0; j < 8; j++) {
            float2 p = up2(acc2[ip][j]);
            accf[2 * ip][j] = p.x; accf[2 * ip + 1][j] = p.y;
        }

    double lsse = 0.0;
#pragma unroll
    for (int i = 0; i < 8; i++) {
        size_t row = (size_t)(bm + trow + i);
        const float* inp = IN + row * DIM + bn + tcol;
        float* qp = Q + row * DIM + bn + tcol;
        float4 in0 = *(const float4*)inp;
        float4 in1 = *(const float4*)(inp + 4);
        float inr[8] = {in0.x, in0.y, in0.z, in0.w, in1.x, in1.y, in1.z, in1.w};
#pragma unroll
        for (int j = 0; j < 8; j++) {
            float q = accf[i][j];
            float diff = q - inr[j];
            lsse += (double)(diff * diff);
            qp[j] = inr[j] + (q - inr[j]);
        }
    }
    sred[tid] = lsse;
    __syncthreads();
    for (int s = 128; s; s >>= 1) {
        if (tid < s) sred[tid] += sred[tid + s];
        __syncthreads();
    }
    if (tid == 0) atomicAdd(&g_sse, sred[0]);
}

// ---------------- finalize ----------------
__global__ void finalize_kernel(float* __restrict__ loss_ptr,
                                float* __restrict__ ppl_ptr)
{
    __shared__ float sred[512];
    int tid = threadIdx.x;
    float avg = g_colsum[tid] * (1.f / (float)NTOK);
    sred[tid] = avg * logf(avg + 1e-10f);
    __syncthreads();
    for (int s = 256; s; s >>= 1) {
        if (tid < s) sred[tid] += sred[tid + s];
        __syncthreads();
    }
    if (tid == 0) {
        *ppl_ptr  = expf(-sred[0]);
        *loss_ptr = (float)(1.25 * g_sse * (1.0 / ((double)NTOK * (double)DIM)));
    }
}

extern "C" void kernel_launch(void* const* d_in, const int* in_sizes, int n_in,
                              void* d_out, int out_size)
{
    (void)in_sizes; (void)n_in; (void)out_size;
    const float* x   = (const float*)d_in[0];
    const float* mW  = (const float*)d_in[1];
    const float* mb  = (const float*)d_in[2];
    const float* lW  = (const float*)d_in[3];
    const float* lb  = (const float*)d_in[4];
    const float* emb = (const float*)d_in[5];

    float* o         = (float*)d_out;
    float* loss_ptr  = o;
    float* q_ptr     = o + 1;
    float* ppl_ptr   = o + 1 + NDsz;
    float* probs_ptr = o + 2 + NDsz;

    dim3 g4(KCB / 128, NTOK / 128);

    init_kernel<<<256, 256>>>();
    rownorm2_kernel<<<KCB / 8, 256>>>(emb);                            // enorm
    sgemm_bias_kernel<<<g4, 256>>>(x, mW, mb, 0, 0, NTOK, DIM, DIM);   // x + fused xnorm
    sgemm_bias_kernel<<<g4, 256>>>(nullptr, lW, lb, 1, 1, NTOK, KCB, DIM); // z
    gemm_prob_kernel<<<g4, 256>>>(emb);                                // unnorm prob
    normalize_kernel<<<NTOK / 32, 256>>>(probs_ptr);                   // Pout + colsum + rinv
    gemm_quant_kernel<<<dim3(DIM / 128, NTOK / 128), 256>>>(emb, x, q_ptr);
    finalize_kernel<<<1, 512>>>(loss_ptr, ppl_ptr);
}